// round 7
// baseline (speedup 1.0000x reference)
#include <cuda_runtime.h>
#include <cuda_bf16.h>
#include <cstdint>
#include <cstddef>

// ---------------------------------------------------------------------------
// Neural CDE classifier, ONE persistent clustered kernel + warp-level bf16
// mma.sync (3-pass hi/lo split ~ fp32 accuracy) for the big vf GEMM.
// grid = 128 CTAs = 16 clusters x 8, 512 thr/CTA, 1 CTA/SM.
// Cluster owns 32 batch elements; vf_W2 (2048x128) row-sliced 256 rows/CTA,
// stored as STATIC bf16 hi/lo [256][136] (row pad 272B -> conflict-free).
// Per RK4 substep:
//   L0 slice (scalar) -> allgather h0
//   L1 slice (scalar) -> allgather h1 as bf16 hi/lo into B operand [32][136]
//   16 warps x 96 mma.m16n8k16 (8 k-steps x 4 n-tiles x 3 hi/lo passes)
//   epilogue: tanh(+bias), dx contraction, warp butterfly over d, warp-pair
//   combine in smem, allgather k -> RK4 combine.  dt cancels; times unused.
// ---------------------------------------------------------------------------

typedef unsigned long long ull;

namespace {
constexpr int NSTEPS = 2047;
constexpr int KP2 = 272;   // padded row stride in BYTES (136 bf16)

// byte offsets in dynamic smem
constexpr int SB_AH = 0;        // 69632  W2 hi bf16 [256][136]
constexpr int SB_AL = 69632;    // 69632  W2 lo bf16 [256][136]
constexpr int SB_BH = 139264;   // 8704   h1 hi bf16 [32 b][136 k]
constexpr int SB_BL = 147968;   // 8704   h1 lo
constexpr int SB_W1 = 156672;   // 8192   fp32 W1 slice [16][128]
constexpr int SB_W0 = 164864;   // 4096   fp32 W0 slice [16][64]
constexpr int SB_B0 = 168960;   // 64
constexpr int SB_B1 = 169024;   // 64
constexpr int SB_Y  = 169088;   // 8192   y   [64][32] fp32
constexpr int SB_YIN= 177280;   // 8192   yin
constexpr int SB_KC = 185472;   // 8192   k   [64][32]
constexpr int SB_H0 = 193664;   // 16384  h0  [128][32] fp32
constexpr int SB_DX = 210048;   // 4224   dx  [32][33] fp32
constexpr int SB_KP = 214272;   // 2048   k partials [16 warp][32 b]
constexpr int SMEM_BYTES = 216320;
}

__device__ __forceinline__ uint32_t s2u(const void* p) {
    return (uint32_t)__cvta_generic_to_shared(p);
}
__device__ __forceinline__ uint32_t mapa_u(uint32_t laddr, int rank) {
    uint32_t r;
    asm("mapa.shared::cluster.u32 %0, %1, %2;" : "=r"(r) : "r"(laddr), "r"(rank));
    return r;
}
__device__ __forceinline__ void st_cluster32(uint32_t raddr, float v) {
    asm volatile("st.shared::cluster.f32 [%0], %1;" :: "r"(raddr), "f"(v) : "memory");
}
__device__ __forceinline__ void st_cluster16(uint32_t raddr, unsigned short v) {
    asm volatile("st.shared::cluster.b16 [%0], %1;" :: "r"(raddr), "h"(v) : "memory");
}
__device__ __forceinline__ void cluster_sync_() {
    asm volatile("barrier.cluster.arrive.aligned;" ::: "memory");
    asm volatile("barrier.cluster.wait.aligned;" ::: "memory");
}
__device__ __forceinline__ float tanh_f(float x) {
    float ax = fabsf(x);
    float e  = __expf(-2.0f * ax);
    float r  = __fdividef(1.0f - e, 1.0f + e);
    return copysignf(r, x);
}
__device__ __forceinline__ float gelu_f(float x) {
    float x3 = x * x * x;
    float t  = tanh_f(0.7978845608028654f * fmaf(0.044715f, x3, x));
    return 0.5f * x * (1.0f + t);
}
__device__ __forceinline__ void ldsm4(uint32_t (&r)[4], uint32_t addr) {
    asm volatile("ldmatrix.sync.aligned.m8n8.x4.shared.b16 {%0,%1,%2,%3}, [%4];"
                 : "=r"(r[0]), "=r"(r[1]), "=r"(r[2]), "=r"(r[3]) : "r"(addr));
}
__device__ __forceinline__ void mma16816(float (&c)[4], const uint32_t (&a)[4],
                                         uint32_t b0, uint32_t b1) {
    asm volatile(
        "mma.sync.aligned.m16n8k16.row.col.f32.bf16.bf16.f32 "
        "{%0,%1,%2,%3}, {%4,%5,%6,%7}, {%8,%9}, {%0,%1,%2,%3};"
        : "+f"(c[0]), "+f"(c[1]), "+f"(c[2]), "+f"(c[3])
        : "r"(a[0]), "r"(a[1]), "r"(a[2]), "r"(a[3]), "r"(b0), "r"(b1));
}

__global__ void __launch_bounds__(512, 1)
ncde_kernel(const float* __restrict__ xs,
            const float* __restrict__ eW0, const float* __restrict__ eb0,
            const float* __restrict__ eW1, const float* __restrict__ eb1,
            const float* __restrict__ eW2, const float* __restrict__ eb2,
            const float* __restrict__ vW0, const float* __restrict__ vb0,
            const float* __restrict__ vW1, const float* __restrict__ vb1,
            const float* __restrict__ vW2, const float* __restrict__ vb2,
            const float* __restrict__ dW,  const float* __restrict__ db,
            float* __restrict__ out)
{
    extern __shared__ char smc[];
    const int tid   = threadIdx.x;
    const int lane  = tid & 31;
    const int wid   = tid >> 5;          // 0..15
    const int rank  = blockIdx.x & 7;
    const int bbase = (blockIdx.x >> 3) * 32;

    float* sW1 = (float*)(smc + SB_W1);
    float* sW0 = (float*)(smc + SB_W0);
    float* sB0 = (float*)(smc + SB_B0);
    float* sB1 = (float*)(smc + SB_B1);
    float* sY  = (float*)(smc + SB_Y);
    float* sYI = (float*)(smc + SB_YIN);
    float* sKC = (float*)(smc + SB_KC);
    float* sH0 = (float*)(smc + SB_H0);
    float* sDX = (float*)(smc + SB_DX);
    float* sKP = (float*)(smc + SB_KP);

    const uint32_t smem_u = s2u(smc);

    // per-rank DSMEM address deltas (mapa is affine in the local address)
    uint32_t rdelta[8];
    #pragma unroll
    for (int r = 0; r < 8; ++r) rdelta[r] = mapa_u(smem_u, r) - smem_u;

    // xs mapping: thread owns (b = tid>>4, d = 2*(tid&15), +1)
    const int xb  = tid >> 4;
    const int xd2 = tid & 15;
    const float* xsrow = xs + (size_t)(bbase + xb) * 2048 * 32 + xd2 * 2;

    float xc0, xc1;
    {
        float2 v = *reinterpret_cast<const float2*>(xsrow);
        xc0 = v.x; xc1 = v.y;
        sKC[(2 * xd2) * 32 + xb]     = v.x;   // stage xs0 d-major for encoder
        sKC[(2 * xd2 + 1) * 32 + xb] = v.y;
    }

    // ---- encoder weights transposed into A scratch (floats) ----
    float* sE0 = (float*)(smc + SB_AH);          // [32][128]
    float* sE1 = sE0 + 4096;                     // [128][128]
    float* sE2 = sE0 + 20480;                    // [128][64]
    float* sEH = sE0 + 28672;                    // [128][32]
    for (int i = tid; i < 4096;  i += 512) { int r = i & 127, kk = i >> 7; sE0[i] = eW0[r * 32  + kk]; }
    for (int i = tid; i < 16384; i += 512) { int r = i & 127, kk = i >> 7; sE1[i] = eW1[r * 128 + kk]; }
    for (int i = tid; i < 8192;  i += 512) { int r = i & 63,  kk = i >> 6; sE2[i] = eW2[r * 128 + kk]; }
    __syncthreads();

    // ---- encoder (replicated per CTA): sKC(xs0) -> sH0 -> sEH -> sY ----
    {
        int b = lane, rbase = wid * 8;
        float acc[8];
        #pragma unroll
        for (int j = 0; j < 8; ++j) acc[j] = eb0[rbase + j];
        for (int kk = 0; kk < 32; ++kk) {
            float x = sKC[kk * 32 + b];
            #pragma unroll
            for (int j = 0; j < 8; ++j) acc[j] = fmaf(sE0[kk * 128 + rbase + j], x, acc[j]);
        }
        #pragma unroll
        for (int j = 0; j < 8; ++j) sH0[(rbase + j) * 32 + b] = fmaxf(acc[j], 0.0f);
    }
    __syncthreads();
    {
        int b = lane, rbase = wid * 8;
        float acc[8];
        #pragma unroll
        for (int j = 0; j < 8; ++j) acc[j] = eb1[rbase + j];
        for (int kk = 0; kk < 128; ++kk) {
            float x = sH0[kk * 32 + b];
            #pragma unroll
            for (int j = 0; j < 8; ++j) acc[j] = fmaf(sE1[kk * 128 + rbase + j], x, acc[j]);
        }
        #pragma unroll
        for (int j = 0; j < 8; ++j) sEH[(rbase + j) * 32 + b] = fmaxf(acc[j], 0.0f);
    }
    __syncthreads();
    {
        int b = lane, rbase = wid * 4;
        float acc[4];
        #pragma unroll
        for (int j = 0; j < 4; ++j) acc[j] = eb2[rbase + j];
        for (int kk = 0; kk < 128; ++kk) {
            float x = sEH[kk * 32 + b];
            #pragma unroll
            for (int j = 0; j < 4; ++j) acc[j] = fmaf(sE2[kk * 64 + rbase + j], x, acc[j]);
        }
        #pragma unroll
        for (int j = 0; j < 4; ++j) sY[(rbase + j) * 32 + b] = acc[j];
    }
    __syncthreads();

    // ---- build static bf16 hi/lo A operand (overwrites encoder scratch) ----
    for (int i = tid; i < 32768; i += 512) {
        int m = i >> 7, k = i & 127;
        float w = vW2[(size_t)(rank * 256 + m) * 128 + k];
        __nv_bfloat16 hb = __float2bfloat16(w);
        float hf = __bfloat162float(hb);
        __nv_bfloat16 lb = __float2bfloat16(w - hf);
        *(__nv_bfloat16*)(smc + SB_AH + m * KP2 + k * 2) = hb;
        *(__nv_bfloat16*)(smc + SB_AL + m * KP2 + k * 2) = lb;
    }
    for (int i = tid; i < 2048; i += 512) {
        int kk = i & 127, r = i >> 7;
        sW1[i] = vW1[(rank * 16 + r) * 128 + kk];
    }
    for (int i = tid; i < 1024; i += 512) {
        int kk = i & 63, r = i >> 6;
        sW0[i] = vW0[(rank * 16 + r) * 64 + kk];
    }
    if (tid < 16)      sB0[tid]      = vb0[rank * 16 + tid];
    else if (tid < 32) sB1[tid - 16] = vb1[rank * 16 + tid - 16];
    cluster_sync_();

    // ---- per-thread invariants ----
    const int g  = lane >> 2;           // mma group id
    const int tg = lane & 3;            // thread in group
    const float b0s = sB0[wid];
    const float b1s = sB1[wid];
    const uint32_t aH0 = s2u(&sH0[(rank * 16 + wid) * 32 + lane]);
    const int kg = rank * 16 + wid;     // global k row produced by this thread in L1
    const uint32_t aBHw = smem_u + SB_BH + (uint32_t)lane * KP2 + kg * 2;
    const uint32_t aBLw = smem_u + SB_BL + (uint32_t)lane * KP2 + kg * 2;

    // A ldmatrix addresses (per k-step add 32B): rows wid*16 + (lane&15), chunk (lane>>4)*16
    const uint32_t aAH = smem_u + SB_AH + (uint32_t)(wid * 16 + (lane & 15)) * KP2 + (lane >> 4) * 16;
    const uint32_t aAL = aAH + (SB_AL - SB_AH);

    // B manual-load bases: row n = g (within n-tile), col bytes kk*32 + tg*4
    const uint32_t aBH = smem_u + SB_BH + (uint32_t)g * KP2 + tg * 4;
    const uint32_t aBL = aBH + (SB_BL - SB_BH);

    // epilogue invariants
    const float b2a = vb2[rank * 256 + wid * 16 + g];
    const float b2b = vb2[rank * 256 + wid * 16 + g + 8];
    const int d0 = (wid & 1) * 16 + g;
    uint32_t aKC = 0;
    if (wid < 8) aKC = s2u(&sKC[(rank * 8 + wid) * 32 + lane]);

    // ---- main RK4 scan ----
    for (int t = 0; t < NSTEPS; ++t) {
        float2 xn = *reinterpret_cast<const float2*>(xsrow + (size_t)(t + 1) * 32);
        float ks0, ks1, ks2, ks3;

        #pragma unroll
        for (int s = 0; s < 4; ++s) {
            const float* yin = (s == 0) ? sY : sYI;

            // ---- L0: h0[wid][lane] = gelu(W0row . yin + b0), push to 8 ranks
            {
                float a = b0s;
                const float* wrow = sW0 + wid * 64;
                #pragma unroll
                for (int k4 = 0; k4 < 16; ++k4) {
                    float4 w4 = *reinterpret_cast<const float4*>(wrow + k4 * 4);
                    a = fmaf(w4.x, yin[(k4 * 4 + 0) * 32 + lane], a);
                    a = fmaf(w4.y, yin[(k4 * 4 + 1) * 32 + lane], a);
                    a = fmaf(w4.z, yin[(k4 * 4 + 2) * 32 + lane], a);
                    a = fmaf(w4.w, yin[(k4 * 4 + 3) * 32 + lane], a);
                }
                a = gelu_f(a);
                #pragma unroll
                for (int r = 0; r < 8; ++r) st_cluster32(aH0 + rdelta[r], a);
            }
            if (s == 0) {
                float dd0 = xn.x - xc0, dd1 = xn.y - xc1;
                xc0 = xn.x; xc1 = xn.y;
                sDX[(2 * xd2) * 33 + xb]     = dd0;
                sDX[(2 * xd2 + 1) * 33 + xb] = dd1;
            }
            cluster_sync_();  // B1: h0 + dx ready everywhere

            // ---- L1: h1[kg][lane] = gelu(W1row . h0 + b1) -> bf16 hi/lo B op
            {
                float a = b1s;
                const float* wrow = sW1 + wid * 128;
                #pragma unroll 8
                for (int k4 = 0; k4 < 32; ++k4) {
                    float4 w4 = *reinterpret_cast<const float4*>(wrow + k4 * 4);
                    a = fmaf(w4.x, sH0[(k4 * 4 + 0) * 32 + lane], a);
                    a = fmaf(w4.y, sH0[(k4 * 4 + 1) * 32 + lane], a);
                    a = fmaf(w4.z, sH0[(k4 * 4 + 2) * 32 + lane], a);
                    a = fmaf(w4.w, sH0[(k4 * 4 + 3) * 32 + lane], a);
                }
                a = gelu_f(a);
                __nv_bfloat16 hb = __float2bfloat16(a);
                float hf = __bfloat162float(hb);
                __nv_bfloat16 lb = __float2bfloat16(a - hf);
                unsigned short hu = reinterpret_cast<unsigned short&>(hb);
                unsigned short lu = reinterpret_cast<unsigned short&>(lb);
                #pragma unroll
                for (int r = 0; r < 8; ++r) {
                    st_cluster16(aBHw + rdelta[r], hu);
                    st_cluster16(aBLw + rdelta[r], lu);
                }
            }
            cluster_sync_();  // B2: B operand ready everywhere

            // ---- W2 GEMM via mma.sync, 3-pass bf16 hi/lo ----
            float acc[4][4];
            #pragma unroll
            for (int nt = 0; nt < 4; ++nt)
                #pragma unroll
                for (int i = 0; i < 4; ++i) acc[nt][i] = 0.0f;

            #pragma unroll
            for (int kk = 0; kk < 8; ++kk) {
                uint32_t ah[4], al[4];
                ldsm4(ah, aAH + kk * 32);
                ldsm4(al, aAL + kk * 32);
                #pragma unroll
                for (int nt = 0; nt < 4; ++nt) {
                    uint32_t rb = (uint32_t)(nt * 8) * KP2 + kk * 32;
                    uint32_t bh0 = *(const uint32_t*)(smc + (aBH - smem_u) + rb);
                    uint32_t bh1 = *(const uint32_t*)(smc + (aBH - smem_u) + rb + 16);
                    uint32_t bl0 = *(const uint32_t*)(smc + (aBL - smem_u) + rb);
                    uint32_t bl1 = *(const uint32_t*)(smc + (aBL - smem_u) + rb + 16);
                    mma16816(acc[nt], ah, bh0, bh1);   // hi * hi
                    mma16816(acc[nt], ah, bl0, bl1);   // hi * lo
                    mma16816(acc[nt], al, bh0, bh1);   // lo * hi
                }
            }

            // ---- epilogue: tanh(+bias) * dx, reduce over d ----
            {
                float p[8];
                #pragma unroll
                for (int nt = 0; nt < 4; ++nt) {
                    int b0i = nt * 8 + tg * 2;
                    float u00 = tanh_f(acc[nt][0] + b2a);
                    float u01 = tanh_f(acc[nt][1] + b2a);
                    float u10 = tanh_f(acc[nt][2] + b2b);
                    float u11 = tanh_f(acc[nt][3] + b2b);
                    p[nt * 2 + 0] = fmaf(u00, sDX[d0 * 33 + b0i],
                                         u10 * sDX[(d0 + 8) * 33 + b0i]);
                    p[nt * 2 + 1] = fmaf(u01, sDX[d0 * 33 + b0i + 1],
                                         u11 * sDX[(d0 + 8) * 33 + b0i + 1]);
                }
                #pragma unroll
                for (int m = 4; m <= 16; m <<= 1)
                    #pragma unroll
                    for (int i = 0; i < 8; ++i)
                        p[i] += __shfl_xor_sync(0xffffffffu, p[i], m);
                if (lane < 4) {
                    #pragma unroll
                    for (int nt = 0; nt < 4; ++nt) {
                        float2 v = make_float2(p[nt * 2], p[nt * 2 + 1]);
                        *reinterpret_cast<float2*>(&sKP[wid * 32 + nt * 8 + tg * 2]) = v;
                    }
                }
            }
            __syncthreads();
            if (wid < 8) {
                float v = sKP[(2 * wid) * 32 + lane] + sKP[(2 * wid + 1) * 32 + lane];
                #pragma unroll
                for (int r = 0; r < 8; ++r) st_cluster32(aKC + rdelta[r], v);
            }
            cluster_sync_();  // B3: k ready everywhere

            // ---- RK4 combine (thread owns y elements [tid*4, tid*4+4)) ----
            {
                const int f = tid * 4;
                float4 k4 = *reinterpret_cast<float4*>(&sKC[f]);
                if (s == 0) {
                    ks0 = k4.x; ks1 = k4.y; ks2 = k4.z; ks3 = k4.w;
                } else {
                    const float w_s = (s == 3) ? 1.0f : 2.0f;
                    ks0 = fmaf(w_s, k4.x, ks0); ks1 = fmaf(w_s, k4.y, ks1);
                    ks2 = fmaf(w_s, k4.z, ks2); ks3 = fmaf(w_s, k4.w, ks3);
                }
                float4 y4 = *reinterpret_cast<float4*>(&sY[f]);
                if (s < 3) {
                    const float c = (s == 2) ? 1.0f : 0.5f;
                    float4 a;
                    a.x = fmaf(c, k4.x, y4.x); a.y = fmaf(c, k4.y, y4.y);
                    a.z = fmaf(c, k4.z, y4.z); a.w = fmaf(c, k4.w, y4.w);
                    *reinterpret_cast<float4*>(&sYI[f]) = a;
                } else {
                    const float sx = 1.0f / 6.0f;
                    y4.x = fmaf(sx, ks0, y4.x); y4.y = fmaf(sx, ks1, y4.y);
                    y4.z = fmaf(sx, ks2, y4.z); y4.w = fmaf(sx, ks3, y4.w);
                    *reinterpret_cast<float4*>(&sY[f]) = y4;
                }
            }
            __syncthreads();
        }
    }

    // ---- decoder + sigmoid (rank 0 CTA) ----
    if (rank == 0 && tid < 32) {
        float acc = db[0];
        #pragma unroll 8
        for (int r = 0; r < 64; ++r) acc = fmaf(dW[r], sY[r * 32 + tid], acc);
        out[bbase + tid] = __fdividef(1.0f, 1.0f + __expf(-acc));
    }
}

extern "C" void kernel_launch(void* const* d_in, const int* in_sizes, int n_in,
                              void* d_out, int out_size) {
    (void)in_sizes; (void)n_in; (void)out_size;
    const float* xs  = (const float*)d_in[1];
    const float* eW0 = (const float*)d_in[2];
    const float* eb0 = (const float*)d_in[3];
    const float* eW1 = (const float*)d_in[4];
    const float* eb1 = (const float*)d_in[5];
    const float* eW2 = (const float*)d_in[6];
    const float* eb2 = (const float*)d_in[7];
    const float* vW0 = (const float*)d_in[8];
    const float* vb0 = (const float*)d_in[9];
    const float* vW1 = (const float*)d_in[10];
    const float* vb1 = (const float*)d_in[11];
    const float* vW2 = (const float*)d_in[12];
    const float* vb2 = (const float*)d_in[13];
    const float* dW  = (const float*)d_in[14];
    const float* db  = (const float*)d_in[15];
    float* out = (float*)d_out;

    cudaFuncSetAttribute(ncde_kernel, cudaFuncAttributeMaxDynamicSharedMemorySize, SMEM_BYTES);

    cudaLaunchConfig_t cfg = {};
    cfg.gridDim  = dim3(128, 1, 1);
    cfg.blockDim = dim3(512, 1, 1);
    cfg.dynamicSmemBytes = SMEM_BYTES;
    cfg.stream = 0;
    cudaLaunchAttribute attrs[1];
    attrs[0].id = cudaLaunchAttributeClusterDimension;
    attrs[0].val.clusterDim.x = 8;
    attrs[0].val.clusterDim.y = 1;
    attrs[0].val.clusterDim.z = 1;
    cfg.attrs = attrs;
    cfg.numAttrs = 1;

    cudaLaunchKernelEx(&cfg, ncde_kernel,
                       xs, eW0, eb0, eW1, eb1, eW2, eb2,
                       vW0, vb0, vW1, vb1, vW2, vb2, dW, db, out);
}

// round 8
// speedup vs baseline: 1.0276x; 1.0276x over previous
#include <cuda_runtime.h>
#include <cuda_bf16.h>
#include <cstdint>
#include <cstddef>

// ---------------------------------------------------------------------------
// Neural CDE classifier, ONE persistent clustered kernel + warp-level bf16
// mma.sync (3-pass hi/lo split ~ fp32 accuracy) for the big vf GEMM.
// grid = 128 CTAs = 16 clusters x 8, 512 thr/CTA, 1 CTA/SM.
// Cluster owns 32 batch elements; vf_W2 (2048x128) row-sliced 256 rows/CTA,
// stored as STATIC bf16 hi/lo [256][136] (row pad 272B -> conflict-free).
// Per RK4 substep:
//   L0 slice (scalar) -> allgather h0
//   L1 slice (scalar) -> allgather h1 as bf16 hi/lo into B operand [32][136]
//   16 warps x 96 mma.m16n8k16 (8 k-steps x 4 n-tiles x 3 hi/lo passes)
//   epilogue: tanh(+bias), dx contraction, warp butterfly over d, warp-pair
//   combine in smem, allgather k -> RK4 combine.  dt cancels; times unused.
// ---------------------------------------------------------------------------

typedef unsigned long long ull;

namespace {
constexpr int NSTEPS = 2047;
constexpr int KP2 = 272;   // padded row stride in BYTES (136 bf16)

// byte offsets in dynamic smem
constexpr int SB_AH = 0;        // 69632  W2 hi bf16 [256][136]
constexpr int SB_AL = 69632;    // 69632  W2 lo bf16 [256][136]
constexpr int SB_BH = 139264;   // 8704   h1 hi bf16 [32 b][136 k]
constexpr int SB_BL = 147968;   // 8704   h1 lo
constexpr int SB_W1 = 156672;   // 8192   fp32 W1 slice [16][128]
constexpr int SB_W0 = 164864;   // 4096   fp32 W0 slice [16][64]
constexpr int SB_B0 = 168960;   // 64
constexpr int SB_B1 = 169024;   // 64
constexpr int SB_Y  = 169088;   // 8192   y   [64][32] fp32
constexpr int SB_YIN= 177280;   // 8192   yin
constexpr int SB_KC = 185472;   // 8192   k   [64][32]
constexpr int SB_H0 = 193664;   // 16384  h0  [128][32] fp32
constexpr int SB_DX = 210048;   // 4224   dx  [32][33] fp32
constexpr int SB_KP = 214272;   // 2048   k partials [16 warp][32 b]
constexpr int SMEM_BYTES = 216320;
}

__device__ __forceinline__ uint32_t s2u(const void* p) {
    return (uint32_t)__cvta_generic_to_shared(p);
}
__device__ __forceinline__ uint32_t mapa_u(uint32_t laddr, int rank) {
    uint32_t r;
    asm("mapa.shared::cluster.u32 %0, %1, %2;" : "=r"(r) : "r"(laddr), "r"(rank));
    return r;
}
__device__ __forceinline__ void st_cluster32(uint32_t raddr, float v) {
    asm volatile("st.shared::cluster.f32 [%0], %1;" :: "r"(raddr), "f"(v) : "memory");
}
__device__ __forceinline__ void st_cluster16(uint32_t raddr, unsigned short v) {
    asm volatile("st.shared::cluster.b16 [%0], %1;" :: "r"(raddr), "h"(v) : "memory");
}
__device__ __forceinline__ void cluster_sync_() {
    asm volatile("barrier.cluster.arrive.aligned;" ::: "memory");
    asm volatile("barrier.cluster.wait.aligned;" ::: "memory");
}
__device__ __forceinline__ float tanh_f(float x) {
    float ax = fabsf(x);
    float e  = __expf(-2.0f * ax);
    float r  = __fdividef(1.0f - e, 1.0f + e);
    return copysignf(r, x);
}
__device__ __forceinline__ float gelu_f(float x) {
    float x3 = x * x * x;
    float t  = tanh_f(0.7978845608028654f * fmaf(0.044715f, x3, x));
    return 0.5f * x * (1.0f + t);
}
__device__ __forceinline__ void ldsm4(uint32_t (&r)[4], uint32_t addr) {
    asm volatile("ldmatrix.sync.aligned.m8n8.x4.shared.b16 {%0,%1,%2,%3}, [%4];"
                 : "=r"(r[0]), "=r"(r[1]), "=r"(r[2]), "=r"(r[3]) : "r"(addr));
}
__device__ __forceinline__ void mma16816(float (&c)[4], const uint32_t (&a)[4],
                                         uint32_t b0, uint32_t b1) {
    asm volatile(
        "mma.sync.aligned.m16n8k16.row.col.f32.bf16.bf16.f32 "
        "{%0,%1,%2,%3}, {%4,%5,%6,%7}, {%8,%9}, {%0,%1,%2,%3};"
        : "+f"(c[0]), "+f"(c[1]), "+f"(c[2]), "+f"(c[3])
        : "r"(a[0]), "r"(a[1]), "r"(a[2]), "r"(a[3]), "r"(b0), "r"(b1));
}

__global__ void __launch_bounds__(512, 1)
ncde_kernel(const float* __restrict__ xs,
            const float* __restrict__ eW0, const float* __restrict__ eb0,
            const float* __restrict__ eW1, const float* __restrict__ eb1,
            const float* __restrict__ eW2, const float* __restrict__ eb2,
            const float* __restrict__ vW0, const float* __restrict__ vb0,
            const float* __restrict__ vW1, const float* __restrict__ vb1,
            const float* __restrict__ vW2, const float* __restrict__ vb2,
            const float* __restrict__ dW,  const float* __restrict__ db,
            float* __restrict__ out)
{
    extern __shared__ char smc[];
    const int tid   = threadIdx.x;
    const int lane  = tid & 31;
    const int wid   = tid >> 5;          // 0..15
    const int rank  = blockIdx.x & 7;
    const int bbase = (blockIdx.x >> 3) * 32;

    float* sW1 = (float*)(smc + SB_W1);
    float* sW0 = (float*)(smc + SB_W0);
    float* sB0 = (float*)(smc + SB_B0);
    float* sB1 = (float*)(smc + SB_B1);
    float* sY  = (float*)(smc + SB_Y);
    float* sYI = (float*)(smc + SB_YIN);
    float* sKC = (float*)(smc + SB_KC);
    float* sH0 = (float*)(smc + SB_H0);
    float* sDX = (float*)(smc + SB_DX);
    float* sKP = (float*)(smc + SB_KP);

    const uint32_t smem_u = s2u(smc);

    // per-rank DSMEM address deltas (mapa is affine in the local address)
    uint32_t rdelta[8];
    #pragma unroll
    for (int r = 0; r < 8; ++r) rdelta[r] = mapa_u(smem_u, r) - smem_u;

    // xs mapping: thread owns (b = tid>>4, d = 2*(tid&15), +1)
    const int xb  = tid >> 4;
    const int xd2 = tid & 15;
    const float* xsrow = xs + (size_t)(bbase + xb) * 2048 * 32 + xd2 * 2;

    float xc0, xc1;
    {
        float2 v = *reinterpret_cast<const float2*>(xsrow);
        xc0 = v.x; xc1 = v.y;
        sKC[(2 * xd2) * 32 + xb]     = v.x;   // stage xs0 d-major for encoder
        sKC[(2 * xd2 + 1) * 32 + xb] = v.y;
    }

    // ---- encoder weights transposed into A scratch (floats) ----
    float* sE0 = (float*)(smc + SB_AH);          // [32][128]
    float* sE1 = sE0 + 4096;                     // [128][128]
    float* sE2 = sE0 + 20480;                    // [128][64]
    float* sEH = sE0 + 28672;                    // [128][32]
    for (int i = tid; i < 4096;  i += 512) { int r = i & 127, kk = i >> 7; sE0[i] = eW0[r * 32  + kk]; }
    for (int i = tid; i < 16384; i += 512) { int r = i & 127, kk = i >> 7; sE1[i] = eW1[r * 128 + kk]; }
    for (int i = tid; i < 8192;  i += 512) { int r = i & 63,  kk = i >> 6; sE2[i] = eW2[r * 128 + kk]; }
    __syncthreads();

    // ---- encoder (replicated per CTA): sKC(xs0) -> sH0 -> sEH -> sY ----
    {
        int b = lane, rbase = wid * 8;
        float acc[8];
        #pragma unroll
        for (int j = 0; j < 8; ++j) acc[j] = eb0[rbase + j];
        for (int kk = 0; kk < 32; ++kk) {
            float x = sKC[kk * 32 + b];
            #pragma unroll
            for (int j = 0; j < 8; ++j) acc[j] = fmaf(sE0[kk * 128 + rbase + j], x, acc[j]);
        }
        #pragma unroll
        for (int j = 0; j < 8; ++j) sH0[(rbase + j) * 32 + b] = fmaxf(acc[j], 0.0f);
    }
    __syncthreads();
    {
        int b = lane, rbase = wid * 8;
        float acc[8];
        #pragma unroll
        for (int j = 0; j < 8; ++j) acc[j] = eb1[rbase + j];
        for (int kk = 0; kk < 128; ++kk) {
            float x = sH0[kk * 32 + b];
            #pragma unroll
            for (int j = 0; j < 8; ++j) acc[j] = fmaf(sE1[kk * 128 + rbase + j], x, acc[j]);
        }
        #pragma unroll
        for (int j = 0; j < 8; ++j) sEH[(rbase + j) * 32 + b] = fmaxf(acc[j], 0.0f);
    }
    __syncthreads();
    {
        int b = lane, rbase = wid * 4;
        float acc[4];
        #pragma unroll
        for (int j = 0; j < 4; ++j) acc[j] = eb2[rbase + j];
        for (int kk = 0; kk < 128; ++kk) {
            float x = sEH[kk * 32 + b];
            #pragma unroll
            for (int j = 0; j < 4; ++j) acc[j] = fmaf(sE2[kk * 64 + rbase + j], x, acc[j]);
        }
        #pragma unroll
        for (int j = 0; j < 4; ++j) sY[(rbase + j) * 32 + b] = acc[j];
    }
    __syncthreads();

    // ---- build static bf16 hi/lo A operand (overwrites encoder scratch) ----
    for (int i = tid; i < 32768; i += 512) {
        int m = i >> 7, k = i & 127;
        float w = vW2[(size_t)(rank * 256 + m) * 128 + k];
        __nv_bfloat16 hb = __float2bfloat16(w);
        float hf = __bfloat162float(hb);
        __nv_bfloat16 lb = __float2bfloat16(w - hf);
        *(__nv_bfloat16*)(smc + SB_AH + m * KP2 + k * 2) = hb;
        *(__nv_bfloat16*)(smc + SB_AL + m * KP2 + k * 2) = lb;
    }
    for (int i = tid; i < 2048; i += 512) {
        int kk = i & 127, r = i >> 7;
        sW1[i] = vW1[(rank * 16 + r) * 128 + kk];
    }
    for (int i = tid; i < 1024; i += 512) {
        int kk = i & 63, r = i >> 6;
        sW0[i] = vW0[(rank * 16 + r) * 64 + kk];
    }
    if (tid < 16)      sB0[tid]      = vb0[rank * 16 + tid];
    else if (tid < 32) sB1[tid - 16] = vb1[rank * 16 + tid - 16];
    cluster_sync_();

    // ---- per-thread invariants ----
    const int g  = lane >> 2;           // mma group id
    const int tg = lane & 3;            // thread in group
    const float b0s = sB0[wid];
    const float b1s = sB1[wid];
    const uint32_t aH0 = s2u(&sH0[(rank * 16 + wid) * 32 + lane]);
    const int kg = rank * 16 + wid;     // global k row produced by this thread in L1
    const uint32_t aBHw = smem_u + SB_BH + (uint32_t)lane * KP2 + kg * 2;
    const uint32_t aBLw = smem_u + SB_BL + (uint32_t)lane * KP2 + kg * 2;

    // A ldmatrix addresses (per k-step add 32B): rows wid*16 + (lane&15), chunk (lane>>4)*16
    const uint32_t aAH = smem_u + SB_AH + (uint32_t)(wid * 16 + (lane & 15)) * KP2 + (lane >> 4) * 16;
    const uint32_t aAL = aAH + (SB_AL - SB_AH);

    // B manual-load bases: row n = g (within n-tile), col bytes kk*32 + tg*4
    const uint32_t aBH = smem_u + SB_BH + (uint32_t)g * KP2 + tg * 4;
    const uint32_t aBL = aBH + (SB_BL - SB_BH);

    // epilogue invariants
    const float b2a = vb2[rank * 256 + wid * 16 + g];
    const float b2b = vb2[rank * 256 + wid * 16 + g + 8];
    const int d0 = (wid & 1) * 16 + g;
    uint32_t aKC = 0;
    if (wid < 8) aKC = s2u(&sKC[(rank * 8 + wid) * 32 + lane]);

    // ---- main RK4 scan ----
    for (int t = 0; t < NSTEPS; ++t) {
        float2 xn = *reinterpret_cast<const float2*>(xsrow + (size_t)(t + 1) * 32);
        float ks0, ks1, ks2, ks3;

        #pragma unroll
        for (int s = 0; s < 4; ++s) {
            const float* yin = (s == 0) ? sY : sYI;

            // ---- L0: h0[wid][lane] = gelu(W0row . yin + b0), push to 8 ranks
            {
                float a = b0s;
                const float* wrow = sW0 + wid * 64;
                #pragma unroll
                for (int k4 = 0; k4 < 16; ++k4) {
                    float4 w4 = *reinterpret_cast<const float4*>(wrow + k4 * 4);
                    a = fmaf(w4.x, yin[(k4 * 4 + 0) * 32 + lane], a);
                    a = fmaf(w4.y, yin[(k4 * 4 + 1) * 32 + lane], a);
                    a = fmaf(w4.z, yin[(k4 * 4 + 2) * 32 + lane], a);
                    a = fmaf(w4.w, yin[(k4 * 4 + 3) * 32 + lane], a);
                }
                a = gelu_f(a);
                #pragma unroll
                for (int r = 0; r < 8; ++r) st_cluster32(aH0 + rdelta[r], a);
            }
            if (s == 0) {
                float dd0 = xn.x - xc0, dd1 = xn.y - xc1;
                xc0 = xn.x; xc1 = xn.y;
                sDX[(2 * xd2) * 33 + xb]     = dd0;
                sDX[(2 * xd2 + 1) * 33 + xb] = dd1;
            }
            cluster_sync_();  // B1: h0 + dx ready everywhere

            // ---- L1: h1[kg][lane] = gelu(W1row . h0 + b1) -> bf16 hi/lo B op
            {
                float a = b1s;
                const float* wrow = sW1 + wid * 128;
                #pragma unroll 8
                for (int k4 = 0; k4 < 32; ++k4) {
                    float4 w4 = *reinterpret_cast<const float4*>(wrow + k4 * 4);
                    a = fmaf(w4.x, sH0[(k4 * 4 + 0) * 32 + lane], a);
                    a = fmaf(w4.y, sH0[(k4 * 4 + 1) * 32 + lane], a);
                    a = fmaf(w4.z, sH0[(k4 * 4 + 2) * 32 + lane], a);
                    a = fmaf(w4.w, sH0[(k4 * 4 + 3) * 32 + lane], a);
                }
                a = gelu_f(a);
                __nv_bfloat16 hb = __float2bfloat16(a);
                float hf = __bfloat162float(hb);
                __nv_bfloat16 lb = __float2bfloat16(a - hf);
                unsigned short hu = reinterpret_cast<unsigned short&>(hb);
                unsigned short lu = reinterpret_cast<unsigned short&>(lb);
                #pragma unroll
                for (int r = 0; r < 8; ++r) {
                    st_cluster16(aBHw + rdelta[r], hu);
                    st_cluster16(aBLw + rdelta[r], lu);
                }
            }
            cluster_sync_();  // B2: B operand ready everywhere

            // ---- W2 GEMM via mma.sync, 3-pass bf16 hi/lo ----
            float acc[4][4];
            #pragma unroll
            for (int nt = 0; nt < 4; ++nt)
                #pragma unroll
                for (int i = 0; i < 4; ++i) acc[nt][i] = 0.0f;

            #pragma unroll
            for (int kk = 0; kk < 8; ++kk) {
                uint32_t ah[4], al[4];
                ldsm4(ah, aAH + kk * 32);
                ldsm4(al, aAL + kk * 32);
                #pragma unroll
                for (int nt = 0; nt < 4; ++nt) {
                    uint32_t rb = (uint32_t)(nt * 8) * KP2 + kk * 32;
                    uint32_t bh0 = *(const uint32_t*)(smc + (aBH - smem_u) + rb);
                    uint32_t bh1 = *(const uint32_t*)(smc + (aBH - smem_u) + rb + 16);
                    uint32_t bl0 = *(const uint32_t*)(smc + (aBL - smem_u) + rb);
                    uint32_t bl1 = *(const uint32_t*)(smc + (aBL - smem_u) + rb + 16);
                    mma16816(acc[nt], ah, bh0, bh1);   // hi * hi
                    mma16816(acc[nt], ah, bl0, bl1);   // hi * lo
                    mma16816(acc[nt], al, bh0, bh1);   // lo * hi
                }
            }

            // ---- epilogue: tanh(+bias) * dx, reduce over d ----
            {
                float p[8];
                #pragma unroll
                for (int nt = 0; nt < 4; ++nt) {
                    int b0i = nt * 8 + tg * 2;
                    float u00 = tanh_f(acc[nt][0] + b2a);
                    float u01 = tanh_f(acc[nt][1] + b2a);
                    float u10 = tanh_f(acc[nt][2] + b2b);
                    float u11 = tanh_f(acc[nt][3] + b2b);
                    p[nt * 2 + 0] = fmaf(u00, sDX[d0 * 33 + b0i],
                                         u10 * sDX[(d0 + 8) * 33 + b0i]);
                    p[nt * 2 + 1] = fmaf(u01, sDX[d0 * 33 + b0i + 1],
                                         u11 * sDX[(d0 + 8) * 33 + b0i + 1]);
                }
                #pragma unroll
                for (int m = 4; m <= 16; m <<= 1)
                    #pragma unroll
                    for (int i = 0; i < 8; ++i)
                        p[i] += __shfl_xor_sync(0xffffffffu, p[i], m);
                if (lane < 4) {
                    #pragma unroll
                    for (int nt = 0; nt < 4; ++nt) {
                        float2 v = make_float2(p[nt * 2], p[nt * 2 + 1]);
                        *reinterpret_cast<float2*>(&sKP[wid * 32 + nt * 8 + tg * 2]) = v;
                    }
                }
            }
            __syncthreads();
            if (wid < 8) {
                float v = sKP[(2 * wid) * 32 + lane] + sKP[(2 * wid + 1) * 32 + lane];
                #pragma unroll
                for (int r = 0; r < 8; ++r) st_cluster32(aKC + rdelta[r], v);
            }
            cluster_sync_();  // B3: k ready everywhere

            // ---- RK4 combine (thread owns y elements [tid*4, tid*4+4)) ----
            {
                const int f = tid * 4;
                float4 k4 = *reinterpret_cast<float4*>(&sKC[f]);
                if (s == 0) {
                    ks0 = k4.x; ks1 = k4.y; ks2 = k4.z; ks3 = k4.w;
                } else {
                    const float w_s = (s == 3) ? 1.0f : 2.0f;
                    ks0 = fmaf(w_s, k4.x, ks0); ks1 = fmaf(w_s, k4.y, ks1);
                    ks2 = fmaf(w_s, k4.z, ks2); ks3 = fmaf(w_s, k4.w, ks3);
                }
                float4 y4 = *reinterpret_cast<float4*>(&sY[f]);
                if (s < 3) {
                    const float c = (s == 2) ? 1.0f : 0.5f;
                    float4 a;
                    a.x = fmaf(c, k4.x, y4.x); a.y = fmaf(c, k4.y, y4.y);
                    a.z = fmaf(c, k4.z, y4.z); a.w = fmaf(c, k4.w, y4.w);
                    *reinterpret_cast<float4*>(&sYI[f]) = a;
                } else {
                    const float sx = 1.0f / 6.0f;
                    y4.x = fmaf(sx, ks0, y4.x); y4.y = fmaf(sx, ks1, y4.y);
                    y4.z = fmaf(sx, ks2, y4.z); y4.w = fmaf(sx, ks3, y4.w);
                    *reinterpret_cast<float4*>(&sY[f]) = y4;
                }
            }
            __syncthreads();
        }
    }

    // ---- decoder + sigmoid (rank 0 CTA) ----
    if (rank == 0 && tid < 32) {
        float acc = db[0];
        #pragma unroll 8
        for (int r = 0; r < 64; ++r) acc = fmaf(dW[r], sY[r * 32 + tid], acc);
        out[bbase + tid] = __fdividef(1.0f, 1.0f + __expf(-acc));
    }
}

extern "C" void kernel_launch(void* const* d_in, const int* in_sizes, int n_in,
                              void* d_out, int out_size) {
    (void)in_sizes; (void)n_in; (void)out_size;
    const float* xs  = (const float*)d_in[1];
    const float* eW0 = (const float*)d_in[2];
    const float* eb0 = (const float*)d_in[3];
    const float* eW1 = (const float*)d_in[4];
    const float* eb1 = (const float*)d_in[5];
    const float* eW2 = (const float*)d_in[6];
    const float* eb2 = (const float*)d_in[7];
    const float* vW0 = (const float*)d_in[8];
    const float* vb0 = (const float*)d_in[9];
    const float* vW1 = (const float*)d_in[10];
    const float* vb1 = (const float*)d_in[11];
    const float* vW2 = (const float*)d_in[12];
    const float* vb2 = (const float*)d_in[13];
    const float* dW  = (const float*)d_in[14];
    const float* db  = (const float*)d_in[15];
    float* out = (float*)d_out;

    cudaFuncSetAttribute(ncde_kernel, cudaFuncAttributeMaxDynamicSharedMemorySize, SMEM_BYTES);

    cudaLaunchConfig_t cfg = {};
    cfg.gridDim  = dim3(128, 1, 1);
    cfg.blockDim = dim3(512, 1, 1);
    cfg.dynamicSmemBytes = SMEM_BYTES;
    cfg.stream = 0;
    cudaLaunchAttribute attrs[1];
    attrs[0].id = cudaLaunchAttributeClusterDimension;
    attrs[0].val.clusterDim.x = 8;
    attrs[0].val.clusterDim.y = 1;
    attrs[0].val.clusterDim.z = 1;
    cfg.attrs = attrs;
    cfg.numAttrs = 1;

    cudaLaunchKernelEx(&cfg, ncde_kernel,
                       xs, eW0, eb0, eW1, eb1, eW2, eb2,
                       vW0, vb0, vW1, vb1, vW2, vb2, dW, db, out);
}